// round 4
// baseline (speedup 1.0000x reference)
#include <cuda_runtime.h>
#include <cstdint>
#include <cstddef>

#define S_LEN 4096
#define BATCH 8
#define DH    512
#define DIN   2048
#define M_TOT (S_LEN * BATCH)
#define NCTA  128
#define HP    528   // padded hs row (words); 528%32==16 -> conflict-free LDS.128

__device__ float g_seq[(size_t)M_TOT * DH];
__device__ float g_G[(size_t)M_TOT * 3 * DH];
__device__ float g_h[BATCH * DH];
__device__ float g_rh[BATCH * DH];
__device__ unsigned g_bar_cnt;
__device__ unsigned g_bar_gen;

// ---- generic 128x64 fp32 tile GEMM body (A rows remapped via functor-ish flags) ----
__global__ __launch_bounds__(256) void gemm1_kernel(const float* __restrict__ x,
                                                    const float* __restrict__ Wlm) {
    __shared__ float As[128][17], Bs[64][17];
    const int m0 = blockIdx.y * 128, n0 = blockIdx.x * 64, tid = threadIdx.x;
    const int ty = tid >> 4, tx = tid & 15;
    float acc[8][4] = {};
    for (int k0 = 0; k0 < DIN; k0 += 16) {
#pragma unroll
        for (int i = 0; i < 2; i++) {
            int ld = tid + i * 256, r = ld >> 2, q = ld & 3;
            int m = m0 + r, b = m & 7, t = m >> 3;
            float4 v = *reinterpret_cast<const float4*>(x + ((size_t)b * S_LEN + t) * DIN + k0 + q * 4);
            As[r][q*4] = v.x; As[r][q*4+1] = v.y; As[r][q*4+2] = v.z; As[r][q*4+3] = v.w;
        }
        { int r = tid >> 2, q = tid & 3;
          float4 v = *reinterpret_cast<const float4*>(Wlm + (size_t)(n0 + r) * DIN + k0 + q * 4);
          Bs[r][q*4] = v.x; Bs[r][q*4+1] = v.y; Bs[r][q*4+2] = v.z; Bs[r][q*4+3] = v.w; }
        __syncthreads();
#pragma unroll
        for (int kk = 0; kk < 16; kk++) {
            float a[8], bb[4];
#pragma unroll
            for (int i = 0; i < 8; i++) a[i] = As[ty*8+i][kk];
#pragma unroll
            for (int j = 0; j < 4; j++) bb[j] = Bs[tx*4+j][kk];
#pragma unroll
            for (int i = 0; i < 8; i++)
#pragma unroll
                for (int j = 0; j < 4; j++) acc[i][j] = fmaf(a[i], bb[j], acc[i][j]);
        }
        __syncthreads();
    }
#pragma unroll
    for (int i = 0; i < 8; i++)
#pragma unroll
        for (int j = 0; j < 4; j++)
            g_seq[(size_t)(m0 + ty*8+i) * DH + n0 + tx*4+j] = acc[i][j];
}

__global__ __launch_bounds__(256) void gemm2_kernel(const float* __restrict__ Wz,
                                                    const float* __restrict__ Wr,
                                                    const float* __restrict__ Wh) {
    __shared__ float As[128][17], Bs[64][17];
    const int m0 = blockIdx.y * 128, n0 = blockIdx.x * 64, tid = threadIdx.x;
    const int ty = tid >> 4, tx = tid & 15;
    const float* base = (n0 < 512) ? Wz : (n0 < 1024) ? Wr : Wh;
    const int br0 = n0 & 511;
    float acc[8][4] = {};
    for (int k0 = 0; k0 < DH; k0 += 16) {
#pragma unroll
        for (int i = 0; i < 2; i++) {
            int ld = tid + i * 256, r = ld >> 2, q = ld & 3;
            float4 v = *reinterpret_cast<const float4*>(g_seq + (size_t)(m0 + r) * DH + k0 + q * 4);
            As[r][q*4] = v.x; As[r][q*4+1] = v.y; As[r][q*4+2] = v.z; As[r][q*4+3] = v.w;
        }
        { int r = tid >> 2, q = tid & 3;  // x-half: cols [0,512)
          float4 v = *reinterpret_cast<const float4*>(base + (size_t)(br0 + r) * 1024 + k0 + q * 4);
          Bs[r][q*4] = v.x; Bs[r][q*4+1] = v.y; Bs[r][q*4+2] = v.z; Bs[r][q*4+3] = v.w; }
        __syncthreads();
#pragma unroll
        for (int kk = 0; kk < 16; kk++) {
            float a[8], bb[4];
#pragma unroll
            for (int i = 0; i < 8; i++) a[i] = As[ty*8+i][kk];
#pragma unroll
            for (int j = 0; j < 4; j++) bb[j] = Bs[tx*4+j][kk];
#pragma unroll
            for (int i = 0; i < 8; i++)
#pragma unroll
                for (int j = 0; j < 4; j++) acc[i][j] = fmaf(a[i], bb[j], acc[i][j]);
        }
        __syncthreads();
    }
#pragma unroll
    for (int i = 0; i < 8; i++)
#pragma unroll
        for (int j = 0; j < 4; j++)
            g_G[(size_t)(m0 + ty*8+i) * 1536 + n0 + tx*4+j] = acc[i][j];
}

__device__ __forceinline__ void gbar(unsigned& gen) {
    __syncthreads();
    if (threadIdx.x == 0) {
        if (atomicAdd(&g_bar_cnt, 1u) == NCTA - 1) {
            g_bar_cnt = 0; __threadfence();
            atomicAdd(&g_bar_gen, 1u);
        } else {
            while (*(volatile unsigned*)&g_bar_gen == gen) {}
        }
    }
    gen++;
    __syncthreads();
}

__global__ __launch_bounds__(256) void gru_kernel(const float* __restrict__ Wz,
                                                  const float* __restrict__ Wr,
                                                  const float* __restrict__ Wh,
                                                  const float* __restrict__ Wc,
                                                  float* __restrict__ out) {
    __shared__ float wz[4][512], wr[4][512], wh[4][512];
    __shared__ float hs[8][HP];
    __shared__ float part[8][8][8];
    __shared__ float z_s[8][4];
    const int tid = threadIdx.x, j0 = blockIdx.x * 4;

    for (int i = tid; i < 4 * 512; i += 256) {
        int j = i >> 9, c = i & 511;
        wz[j][c] = Wz[(size_t)(j0 + j) * 1024 + 512 + c];
        wr[j][c] = Wr[(size_t)(j0 + j) * 1024 + 512 + c];
        wh[j][c] = Wh[(size_t)(j0 + j) * 1024 + 512 + c];
    }
    for (int i = tid; i < 8 * HP; i += 256) (&hs[0][0])[i] = 0.f;

    unsigned gen = 0;
    if (tid == 0) gen = *(volatile unsigned*)&g_bar_gen;
    __syncthreads();

    const int w = tid >> 5, lane = tid & 31;
    const int b = lane >> 2, kk = lane & 3;

    for (int t = 0; t < S_LEN; t++) {
        float gx1 = 0.f, gx2 = 0.f, h_own = 0.f;
        if (tid < 64) {
            int b2 = tid >> 3, o = tid & 7, jj = o & 3;
            gx1 = g_G[((size_t)t * 8 + b2) * 1536 + ((o < 4) ? 0 : 512) + j0 + jj];
        }
        if (tid < 32) {
            int b2 = tid >> 2, jj = tid & 3;
            gx2 = g_G[((size_t)t * 8 + b2) * 1536 + 1024 + j0 + jj];
            h_own = hs[b2][j0 + jj];
        }
        // stage 1: z & r pre-acts over h
        float acc[8] = {};
#pragma unroll
        for (int c = 0; c < 4; c++) {
            int k = w * 16 + c * 128 + kk * 4;
            float4 h4 = *reinterpret_cast<const float4*>(&hs[b][k]);
#pragma unroll
            for (int o = 0; o < 8; o++) {
                const float* wp = (o < 4) ? &wz[o][k] : &wr[o - 4][k];
                float4 w4 = *reinterpret_cast<const float4*>(wp);
                acc[o] += h4.x*w4.x + h4.y*w4.y + h4.z*w4.z + h4.w*w4.w;
            }
        }
#pragma unroll
        for (int o = 0; o < 8; o++) {
            acc[o] += __shfl_xor_sync(~0u, acc[o], 1);
            acc[o] += __shfl_xor_sync(~0u, acc[o], 2);
        }
        if (kk == 0) {
#pragma unroll
            for (int o = 0; o < 8; o++) part[w][b][o] = acc[o];
        }
        __syncthreads();
        if (tid < 64) {
            int b2 = tid >> 3, o = tid & 7, jj = o & 3;
            float s = gx1;
#pragma unroll
            for (int ww = 0; ww < 8; ww++) s += part[ww][b2][o];
            float v = 1.f / (1.f + expf(-s));
            if (o < 4) z_s[b2][jj] = v;
            else g_rh[b2 * 512 + j0 + jj] = v * hs[b2][j0 + jj];
        }
        __threadfence();
        gbar(gen);
        for (int i = tid; i < 1024; i += 256) {
            int b2 = i >> 7, c4 = i & 127;
            *reinterpret_cast<float4*>(&hs[b2][c4 * 4]) =
                __ldcg(reinterpret_cast<const float4*>(g_rh) + i);
        }
        __syncthreads();
        // stage 2: h' over r*h
        float acc2[4] = {};
#pragma unroll
        for (int c = 0; c < 4; c++) {
            int k = w * 16 + c * 128 + kk * 4;
            float4 r4 = *reinterpret_cast<const float4*>(&hs[b][k]);
#pragma unroll
            for (int o = 0; o < 4; o++) {
                float4 w4 = *reinterpret_cast<const float4*>(&wh[o][k]);
                acc2[o] += r4.x*w4.x + r4.y*w4.y + r4.z*w4.z + r4.w*w4.w;
            }
        }
#pragma unroll
        for (int o = 0; o < 4; o++) {
            acc2[o] += __shfl_xor_sync(~0u, acc2[o], 1);
            acc2[o] += __shfl_xor_sync(~0u, acc2[o], 2);
        }
        if (kk == 0) {
#pragma unroll
            for (int o = 0; o < 4; o++) part[w][b][o] = acc2[o];
        }
        __syncthreads();
        if (tid < 32) {
            int b2 = tid >> 2, jj = tid & 3;
            float s = gx2;
#pragma unroll
            for (int ww = 0; ww < 8; ww++) s += part[ww][b2][jj];
            float hp = tanhf(s), z = z_s[b2][jj];
            g_h[b2 * 512 + j0 + jj] = (1.f - z) * h_own + z * hp;
        }
        __threadfence();
        gbar(gen);
        for (int i = tid; i < 1024; i += 256) {
            int b2 = i >> 7, c4 = i & 127;
            *reinterpret_cast<float4*>(&hs[b2][c4 * 4]) =
                __ldcg(reinterpret_cast<const float4*>(g_h) + i);
        }
        __syncthreads();
    }

    // classifier: every CTA now holds final h in hs; CTA0 writes out [8,10]
    if (blockIdx.x == 0) {
        for (int p = w; p < 80; p += 8) {
            int bb = p / 10, cc = p % 10;
            float s = 0.f;
            for (int j = lane; j < 512; j += 32)
                s += hs[bb][j] * Wc[(size_t)cc * 512 + j];
#pragma unroll
            for (int d = 16; d; d >>= 1) s += __shfl_xor_sync(~0u, s, d);
            if (lane == 0) out[bb * 10 + cc] = s;
        }
    }
}

extern "C" void kernel_launch(void* const* d_in, const int* in_sizes, int n_in,
                              void* d_out, int out_size) {
    const float* x   = (const float*)d_in[0];
    const float* Wlm = (const float*)d_in[1];
    const float* Wz  = (const float*)d_in[2];
    const float* Wr  = (const float*)d_in[3];
    const float* Wh  = (const float*)d_in[4];
    const float* Wc  = (const float*)d_in[5];
    float* out = (float*)d_out;
    gemm1_kernel<<<dim3(8, 256), 256>>>(x, Wlm);
    gemm2_kernel<<<dim3(24, 256), 256>>>(Wz, Wr, Wh);
    gru_kernel<<<NCTA, 256>>>(Wz, Wr, Wh, Wc, out);
}